// round 1
// baseline (speedup 1.0000x reference)
#include <cuda_runtime.h>
#include <cuda_bf16.h>

#define N_NODES 100000
#define D 128

// ---------------- scratch (static device globals; no allocation) ----------------
__device__ float g_h0[(size_t)N_NODES * D];   // h0, later reused for h2
__device__ float g_h1[(size_t)N_NODES * D];
__device__ float g_agg[(size_t)N_NODES * D];
__device__ float g_deg[N_NODES];

// ---------------- zero ----------------
__global__ void zero_kernel(float* __restrict__ p, int n) {
    int i = blockIdx.x * blockDim.x + threadIdx.x;
    int stride = gridDim.x * blockDim.x;
    for (; i < n; i += stride) p[i] = 0.0f;
}

// ---------------- GEMM: C[M,128] = act(A[M,128] @ W[128,128] (+C) (+bias)) ----------------
// block: 256 threads (16x16), tile 128x128, TM=TN=8
template<int BETA, int RELU, int HAS_BIAS>
__global__ void __launch_bounds__(256) gemm_kernel(
    const float* __restrict__ A, const float* __restrict__ W,
    const float* __restrict__ bias, float* __restrict__ C, int M)
{
    __shared__ float Ast[32][128];   // A chunk, transposed [k][m]
    __shared__ float Ws[32][128];    // W chunk [k][n]

    const int tid = threadIdx.x;
    const int tx = tid & 15;         // column group
    const int ty = tid >> 4;         // row group
    const int block_m = blockIdx.x * 128;

    float acc[8][8];
#pragma unroll
    for (int i = 0; i < 8; i++)
#pragma unroll
        for (int j = 0; j < 8; j++) acc[i][j] = 0.0f;

    for (int k0 = 0; k0 < 128; k0 += 32) {
        // stage A: 128 rows x 32 k, store transposed
#pragma unroll
        for (int it = 0; it < 4; it++) {
            int i = tid + it * 256;          // 1024 float4 slots
            int m  = i >> 3;                 // 0..127
            int k4 = (i & 7) << 2;           // 0,4,...,28
            int gm = block_m + m;
            float4 v = make_float4(0.f, 0.f, 0.f, 0.f);
            if (gm < M) v = *(const float4*)(A + (size_t)gm * 128 + k0 + k4);
            Ast[k4 + 0][m] = v.x;
            Ast[k4 + 1][m] = v.y;
            Ast[k4 + 2][m] = v.z;
            Ast[k4 + 3][m] = v.w;
        }
        // stage W: 32 k-rows x 128 n
#pragma unroll
        for (int it = 0; it < 4; it++) {
            int i = tid + it * 256;          // 1024 float4 slots
            int k  = i >> 5;                 // 0..31
            int n4 = (i & 31) << 2;          // 0..124
            *(float4*)&Ws[k][n4] = *(const float4*)(W + (size_t)(k0 + k) * 128 + n4);
        }
        __syncthreads();

#pragma unroll 8
        for (int k = 0; k < 32; k++) {
            float a[8], b[8];
            *(float4*)&a[0] = *(float4*)&Ast[k][ty * 8];
            *(float4*)&a[4] = *(float4*)&Ast[k][ty * 8 + 4];
            *(float4*)&b[0] = *(float4*)&Ws[k][tx * 8];
            *(float4*)&b[4] = *(float4*)&Ws[k][tx * 8 + 4];
#pragma unroll
            for (int i = 0; i < 8; i++)
#pragma unroll
                for (int j = 0; j < 8; j++)
                    acc[i][j] = fmaf(a[i], b[j], acc[i][j]);
        }
        __syncthreads();
    }

    // epilogue
    const int gn = tx * 8;
#pragma unroll
    for (int i = 0; i < 8; i++) {
        int gm = block_m + ty * 8 + i;
        if (gm >= M) continue;
        float4* cp = (float4*)(C + (size_t)gm * 128 + gn);
#pragma unroll
        for (int jj = 0; jj < 2; jj++) {
            float4 r;
            r.x = acc[i][jj * 4 + 0];
            r.y = acc[i][jj * 4 + 1];
            r.z = acc[i][jj * 4 + 2];
            r.w = acc[i][jj * 4 + 3];
            if (BETA) {
                float4 o = cp[jj];
                r.x += o.x; r.y += o.y; r.z += o.z; r.w += o.w;
            }
            if (HAS_BIAS) {
                const float4 bb = *(const float4*)(bias + gn + jj * 4);
                r.x += bb.x; r.y += bb.y; r.z += bb.z; r.w += bb.w;
            }
            if (RELU) {
                r.x = fmaxf(r.x, 0.f); r.y = fmaxf(r.y, 0.f);
                r.z = fmaxf(r.z, 0.f); r.w = fmaxf(r.w, 0.f);
            }
            cp[jj] = r;
        }
    }
}

// ---------------- edge scatter: one warp per edge ----------------
__global__ void scatter_kernel(const float* __restrict__ h,
                               const int* __restrict__ src,
                               const int* __restrict__ dst,
                               float* __restrict__ agg,
                               float* __restrict__ deg, int E)
{
    int gw = (blockIdx.x * blockDim.x + threadIdx.x) >> 5;
    int lane = threadIdx.x & 31;
    if (gw >= E) return;
    int s = src[gw];
    int d = dst[gw];
    float4 v = ((const float4*)(h + (size_t)s * 128))[lane];
    float* p = agg + (size_t)d * 128 + lane * 4;
    atomicAdd(p + 0, v.x);
    atomicAdd(p + 1, v.y);
    atomicAdd(p + 2, v.z);
    atomicAdd(p + 3, v.w);
    if (lane == 0) atomicAdd(deg + d, 1.0f);
}

// ---------------- agg -> mean (in place) ----------------
__global__ void mean_kernel(float* __restrict__ agg, const float* __restrict__ deg, int n4) {
    int i = blockIdx.x * blockDim.x + threadIdx.x;   // over N*32 float4s
    if (i >= n4) return;
    int node = i >> 5;
    float inv = 1.0f / fmaxf(deg[node], 1.0f);
    float4* p = (float4*)agg + i;
    float4 v = *p;
    v.x *= inv; v.y *= inv; v.z *= inv; v.w *= inv;
    *p = v;
}

// ---------------- edge scores: one warp per pair ----------------
__global__ void score_kernel(const float* __restrict__ h,
                             const int* __restrict__ a,
                             const int* __restrict__ b,
                             float* __restrict__ out, int P)
{
    int gw = (blockIdx.x * blockDim.x + threadIdx.x) >> 5;
    int lane = threadIdx.x & 31;
    if (gw >= P) return;
    int ia = a[gw];
    int ib = b[gw];
    float4 va = ((const float4*)(h + (size_t)ia * 128))[lane];
    float4 vb = ((const float4*)(h + (size_t)ib * 128))[lane];
    float s = va.x * vb.x + va.y * vb.y + va.z * vb.z + va.w * vb.w;
#pragma unroll
    for (int o = 16; o > 0; o >>= 1) s += __shfl_xor_sync(0xFFFFFFFFu, s, o);
    if (lane == 0) out[gw] = s;
}

// ---------------- launch ----------------
extern "C" void kernel_launch(void* const* d_in, const int* in_sizes, int n_in,
                              void* d_out, int out_size)
{
    const float* feat    = (const float*)d_in[0];
    const int*   e0s     = (const int*)d_in[1];
    const int*   e0d     = (const int*)d_in[2];
    const int*   e1s     = (const int*)d_in[3];
    const int*   e1d     = (const int*)d_in[4];
    const int*   ps      = (const int*)d_in[5];
    const int*   pd      = (const int*)d_in[6];
    const int*   ns      = (const int*)d_in[7];
    const int*   nd      = (const int*)d_in[8];
    const float* w_proj  = (const float*)d_in[9];
    const float* b_proj  = (const float*)d_in[10];
    const float* w_self1 = (const float*)d_in[11];
    const float* w_neigh1= (const float*)d_in[12];
    const float* b1      = (const float*)d_in[13];
    const float* w_self2 = (const float*)d_in[14];
    const float* w_neigh2= (const float*)d_in[15];
    const float* b2      = (const float*)d_in[16];

    const int E0 = in_sizes[1];
    const int E1 = in_sizes[3];
    const int P  = in_sizes[5];
    const int Q  = in_sizes[7];
    float* out = (float*)d_out;

    float *h0, *h1, *agg, *deg;
    cudaGetSymbolAddress((void**)&h0,  g_h0);
    cudaGetSymbolAddress((void**)&h1,  g_h1);
    cudaGetSymbolAddress((void**)&agg, g_agg);
    cudaGetSymbolAddress((void**)&deg, g_deg);

    const int gemm_grid = (N_NODES + 127) / 128;
    const int nd_elems  = N_NODES * D;
    const int mean_grid = (N_NODES * 32 + 255) / 256;

    // h0 = relu(feat @ w_proj + b_proj)
    gemm_kernel<0, 1, 1><<<gemm_grid, 256>>>(feat, w_proj, b_proj, h0, N_NODES);

    // ---- layer 1 ----
    zero_kernel<<<4096, 256>>>(agg, nd_elems);
    zero_kernel<<<256, 256>>>(deg, N_NODES);
    {
        int blocks = (E0 + 7) / 8;   // 8 warps/block, 1 warp/edge
        scatter_kernel<<<blocks, 256>>>(h0, e0s, e0d, agg, deg, E0);
    }
    mean_kernel<<<mean_grid, 256>>>(agg, deg, N_NODES * 32);
    gemm_kernel<0, 0, 0><<<gemm_grid, 256>>>(h0, w_self1, nullptr, h1, N_NODES);
    gemm_kernel<1, 1, 1><<<gemm_grid, 256>>>(agg, w_neigh1, b1, h1, N_NODES);

    // ---- layer 2 ----
    zero_kernel<<<4096, 256>>>(agg, nd_elems);
    zero_kernel<<<256, 256>>>(deg, N_NODES);
    {
        int blocks = (E1 + 7) / 8;
        scatter_kernel<<<blocks, 256>>>(h1, e1s, e1d, agg, deg, E1);
    }
    mean_kernel<<<mean_grid, 256>>>(agg, deg, N_NODES * 32);
    // h2 reuses h0 buffer
    gemm_kernel<0, 0, 0><<<gemm_grid, 256>>>(h1, w_self2, nullptr, h0, N_NODES);
    gemm_kernel<1, 0, 1><<<gemm_grid, 256>>>(agg, w_neigh2, b2, h0, N_NODES);

    // ---- scores ----
    {
        int blocks = (P + 7) / 8;
        score_kernel<<<blocks, 256>>>(h0, ps, pd, out, P);
    }
    {
        int blocks = (Q + 7) / 8;
        score_kernel<<<blocks, 256>>>(h0, ns, nd, out + P, Q);
    }
}

// round 2
// speedup vs baseline: 2.0387x; 2.0387x over previous
#include <cuda_runtime.h>
#include <cuda_bf16.h>

#define N_NODES 100000
#define D 128
#define E_MAX 1600000
#define SCAN_CHUNK 1024
#define SCAN_NB ((N_NODES + SCAN_CHUNK - 1) / SCAN_CHUNK)   // 98

// ---------------- scratch (static device globals; no allocation) ----------------
__device__ float g_h0[(size_t)N_NODES * D];   // h0, later reused for h2
__device__ float g_h1[(size_t)N_NODES * D];
__device__ float g_agg[(size_t)N_NODES * D];
__device__ int   g_hist[N_NODES];
__device__ int   g_rowptr[N_NODES + 1];
__device__ int   g_cursor[N_NODES];
__device__ int   g_csr[E_MAX];
__device__ int   g_blocksums[SCAN_NB];

// ---------------- zero int ----------------
__global__ void zero_int_kernel(int* __restrict__ p, int n) {
    int i = blockIdx.x * blockDim.x + threadIdx.x;
    int stride = gridDim.x * blockDim.x;
    for (; i < n; i += stride) p[i] = 0;
}

// ---------------- histogram of dst ----------------
__global__ void hist_kernel(const int* __restrict__ dst, int* __restrict__ hist, int E) {
    int i = blockIdx.x * blockDim.x + threadIdx.x;
    if (i >= E) return;
    atomicAdd(&hist[dst[i]], 1);
}

// ---------------- scan phase 1: per-block sums ----------------
__global__ void scan1_kernel(const int* __restrict__ hist, int* __restrict__ blocksums) {
    __shared__ int sh[256];
    int t = threadIdx.x;
    int base = blockIdx.x * SCAN_CHUNK + t * 4;
    int s = 0;
#pragma unroll
    for (int j = 0; j < 4; j++) {
        int idx = base + j;
        if (idx < N_NODES) s += hist[idx];
    }
    sh[t] = s;
    __syncthreads();
    for (int o = 128; o > 0; o >>= 1) {
        if (t < o) sh[t] += sh[t + o];
        __syncthreads();
    }
    if (t == 0) blocksums[blockIdx.x] = sh[0];
}

// ---------------- scan phase 2: exclusive scan of block sums (tiny) ----------------
__global__ void scan2_kernel(int* __restrict__ blocksums, int nb, int* __restrict__ rowptr) {
    if (threadIdx.x == 0 && blockIdx.x == 0) {
        int run = 0;
        for (int i = 0; i < nb; i++) {
            int v = blocksums[i];
            blocksums[i] = run;
            run += v;
        }
        rowptr[N_NODES] = run;
    }
}

// ---------------- scan phase 3: local exclusive scan + write rowptr & cursor ----------------
__global__ void scan3_kernel(const int* __restrict__ hist, const int* __restrict__ blocksums,
                             int* __restrict__ rowptr, int* __restrict__ cursor) {
    __shared__ int sh[256];
    int t = threadIdx.x;
    int base = blockIdx.x * SCAN_CHUNK + t * 4;
    int v[4];
    int s = 0;
#pragma unroll
    for (int j = 0; j < 4; j++) {
        int idx = base + j;
        v[j] = (idx < N_NODES) ? hist[idx] : 0;
        s += v[j];
    }
    sh[t] = s;
    __syncthreads();
    // Hillis-Steele inclusive scan over 256 thread sums
    int val = s;
    for (int o = 1; o < 256; o <<= 1) {
        int other = (t >= o) ? sh[t - o] : 0;
        __syncthreads();
        val += other;
        sh[t] = val;
        __syncthreads();
    }
    int texcl = val - s;                       // exclusive
    int off = blocksums[blockIdx.x] + texcl;
#pragma unroll
    for (int j = 0; j < 4; j++) {
        int idx = base + j;
        if (idx < N_NODES) {
            rowptr[idx] = off;
            cursor[idx] = off;
        }
        off += v[j];
    }
}

// ---------------- fill CSR ----------------
__global__ void fill_kernel(const int* __restrict__ src, const int* __restrict__ dst,
                            int* __restrict__ cursor, int* __restrict__ csr, int E) {
    int i = blockIdx.x * blockDim.x + threadIdx.x;
    if (i >= E) return;
    int p = atomicAdd(&cursor[dst[i]], 1);
    csr[p] = src[i];
}

// ---------------- gather + mean: one warp per dst node ----------------
__global__ void __launch_bounds__(256) gather_mean_kernel(
    const float* __restrict__ h, const int* __restrict__ csr,
    const int* __restrict__ rowptr, float* __restrict__ agg)
{
    int gw = (blockIdx.x * blockDim.x + threadIdx.x) >> 5;
    int lane = threadIdx.x & 31;
    if (gw >= N_NODES) return;
    int n0 = rowptr[gw];
    int n1 = rowptr[gw + 1];
    float4 acc = make_float4(0.f, 0.f, 0.f, 0.f);
    for (int base = n0; base < n1; base += 32) {
        int idx = base + lane;
        int sj = (idx < n1) ? csr[idx] : 0;
        int cnt = min(32, n1 - base);
        for (int t = 0; t < cnt; t++) {
            int s = __shfl_sync(0xFFFFFFFFu, sj, t);
            float4 v = ((const float4*)(h + (size_t)s * 128))[lane];
            acc.x += v.x; acc.y += v.y; acc.z += v.z; acc.w += v.w;
        }
    }
    float inv = (n1 > n0) ? 1.0f / (float)(n1 - n0) : 0.0f;
    acc.x *= inv; acc.y *= inv; acc.z *= inv; acc.w *= inv;
    ((float4*)(agg + (size_t)gw * 128))[lane] = acc;
}

// ---------------- single GEMM: C = act(A @ W + bias) ----------------
template<int RELU>
__global__ void __launch_bounds__(256) gemm_kernel(
    const float* __restrict__ A, const float* __restrict__ W,
    const float* __restrict__ bias, float* __restrict__ C, int M)
{
    __shared__ float Ast[32][128];
    __shared__ float Ws[32][128];

    const int tid = threadIdx.x;
    const int tx = tid & 15;
    const int ty = tid >> 4;
    const int block_m = blockIdx.x * 128;

    float acc[8][8];
#pragma unroll
    for (int i = 0; i < 8; i++)
#pragma unroll
        for (int j = 0; j < 8; j++) acc[i][j] = 0.0f;

    for (int k0 = 0; k0 < 128; k0 += 32) {
#pragma unroll
        for (int it = 0; it < 4; it++) {
            int i = tid + it * 256;
            int m = i >> 3;
            int k4 = (i & 7) << 2;
            int gm = block_m + m;
            float4 v = make_float4(0.f, 0.f, 0.f, 0.f);
            if (gm < M) v = *(const float4*)(A + (size_t)gm * 128 + k0 + k4);
            Ast[k4 + 0][m] = v.x; Ast[k4 + 1][m] = v.y;
            Ast[k4 + 2][m] = v.z; Ast[k4 + 3][m] = v.w;
        }
#pragma unroll
        for (int it = 0; it < 4; it++) {
            int i = tid + it * 256;
            int k = i >> 5;
            int n4 = (i & 31) << 2;
            *(float4*)&Ws[k][n4] = *(const float4*)(W + (size_t)(k0 + k) * 128 + n4);
        }
        __syncthreads();
#pragma unroll 8
        for (int k = 0; k < 32; k++) {
            float a[8], b[8];
            *(float4*)&a[0] = *(float4*)&Ast[k][ty * 8];
            *(float4*)&a[4] = *(float4*)&Ast[k][ty * 8 + 4];
            *(float4*)&b[0] = *(float4*)&Ws[k][tx * 8];
            *(float4*)&b[4] = *(float4*)&Ws[k][tx * 8 + 4];
#pragma unroll
            for (int i = 0; i < 8; i++)
#pragma unroll
                for (int j = 0; j < 8; j++)
                    acc[i][j] = fmaf(a[i], b[j], acc[i][j]);
        }
        __syncthreads();
    }

    const int gn = tx * 8;
#pragma unroll
    for (int i = 0; i < 8; i++) {
        int gm = block_m + ty * 8 + i;
        if (gm >= M) continue;
        float4* cp = (float4*)(C + (size_t)gm * 128 + gn);
#pragma unroll
        for (int jj = 0; jj < 2; jj++) {
            float4 r;
            r.x = acc[i][jj * 4 + 0]; r.y = acc[i][jj * 4 + 1];
            r.z = acc[i][jj * 4 + 2]; r.w = acc[i][jj * 4 + 3];
            const float4 bb = *(const float4*)(bias + gn + jj * 4);
            r.x += bb.x; r.y += bb.y; r.z += bb.z; r.w += bb.w;
            if (RELU) {
                r.x = fmaxf(r.x, 0.f); r.y = fmaxf(r.y, 0.f);
                r.z = fmaxf(r.z, 0.f); r.w = fmaxf(r.w, 0.f);
            }
            cp[jj] = r;
        }
    }
}

// ---------------- fused dual GEMM: C = act(A1 @ W1 + A2 @ W2 + bias) ----------------
template<int RELU>
__global__ void __launch_bounds__(256) dual_gemm_kernel(
    const float* __restrict__ A1, const float* __restrict__ W1,
    const float* __restrict__ A2, const float* __restrict__ W2,
    const float* __restrict__ bias, float* __restrict__ C, int M)
{
    __shared__ float Ast1[16][128];
    __shared__ float Ast2[16][128];
    __shared__ float Ws1[16][128];
    __shared__ float Ws2[16][128];

    const int tid = threadIdx.x;
    const int tx = tid & 15;
    const int ty = tid >> 4;
    const int block_m = blockIdx.x * 128;

    float acc[8][8];
#pragma unroll
    for (int i = 0; i < 8; i++)
#pragma unroll
        for (int j = 0; j < 8; j++) acc[i][j] = 0.0f;

    for (int k0 = 0; k0 < 128; k0 += 16) {
        // stage A1/A2: 128 rows x 16 k (512 float4 slots each -> 2 iters)
#pragma unroll
        for (int it = 0; it < 2; it++) {
            int i = tid + it * 256;
            int m = i >> 2;                 // 0..127
            int k4 = (i & 3) << 2;          // 0,4,8,12
            int gm = block_m + m;
            float4 v1 = make_float4(0.f, 0.f, 0.f, 0.f);
            float4 v2 = make_float4(0.f, 0.f, 0.f, 0.f);
            if (gm < M) {
                v1 = *(const float4*)(A1 + (size_t)gm * 128 + k0 + k4);
                v2 = *(const float4*)(A2 + (size_t)gm * 128 + k0 + k4);
            }
            Ast1[k4 + 0][m] = v1.x; Ast1[k4 + 1][m] = v1.y;
            Ast1[k4 + 2][m] = v1.z; Ast1[k4 + 3][m] = v1.w;
            Ast2[k4 + 0][m] = v2.x; Ast2[k4 + 1][m] = v2.y;
            Ast2[k4 + 2][m] = v2.z; Ast2[k4 + 3][m] = v2.w;
        }
        // stage W1/W2: 16 k-rows x 128 n (512 float4 slots each -> 2 iters)
#pragma unroll
        for (int it = 0; it < 2; it++) {
            int i = tid + it * 256;
            int k = i >> 5;                 // 0..15
            int n4 = (i & 31) << 2;
            *(float4*)&Ws1[k][n4] = *(const float4*)(W1 + (size_t)(k0 + k) * 128 + n4);
            *(float4*)&Ws2[k][n4] = *(const float4*)(W2 + (size_t)(k0 + k) * 128 + n4);
        }
        __syncthreads();
#pragma unroll
        for (int k = 0; k < 16; k++) {
            float a1[8], a2[8], b1[8], b2[8];
            *(float4*)&a1[0] = *(float4*)&Ast1[k][ty * 8];
            *(float4*)&a1[4] = *(float4*)&Ast1[k][ty * 8 + 4];
            *(float4*)&b1[0] = *(float4*)&Ws1[k][tx * 8];
            *(float4*)&b1[4] = *(float4*)&Ws1[k][tx * 8 + 4];
            *(float4*)&a2[0] = *(float4*)&Ast2[k][ty * 8];
            *(float4*)&a2[4] = *(float4*)&Ast2[k][ty * 8 + 4];
            *(float4*)&b2[0] = *(float4*)&Ws2[k][tx * 8];
            *(float4*)&b2[4] = *(float4*)&Ws2[k][tx * 8 + 4];
#pragma unroll
            for (int i = 0; i < 8; i++)
#pragma unroll
                for (int j = 0; j < 8; j++) {
                    acc[i][j] = fmaf(a1[i], b1[j], acc[i][j]);
                    acc[i][j] = fmaf(a2[i], b2[j], acc[i][j]);
                }
        }
        __syncthreads();
    }

    const int gn = tx * 8;
#pragma unroll
    for (int i = 0; i < 8; i++) {
        int gm = block_m + ty * 8 + i;
        if (gm >= M) continue;
        float4* cp = (float4*)(C + (size_t)gm * 128 + gn);
#pragma unroll
        for (int jj = 0; jj < 2; jj++) {
            float4 r;
            r.x = acc[i][jj * 4 + 0]; r.y = acc[i][jj * 4 + 1];
            r.z = acc[i][jj * 4 + 2]; r.w = acc[i][jj * 4 + 3];
            const float4 bb = *(const float4*)(bias + gn + jj * 4);
            r.x += bb.x; r.y += bb.y; r.z += bb.z; r.w += bb.w;
            if (RELU) {
                r.x = fmaxf(r.x, 0.f); r.y = fmaxf(r.y, 0.f);
                r.z = fmaxf(r.z, 0.f); r.w = fmaxf(r.w, 0.f);
            }
            cp[jj] = r;
        }
    }
}

// ---------------- edge scores: one warp per pair ----------------
__global__ void score_kernel(const float* __restrict__ h,
                             const int* __restrict__ a,
                             const int* __restrict__ b,
                             float* __restrict__ out, int P)
{
    int gw = (blockIdx.x * blockDim.x + threadIdx.x) >> 5;
    int lane = threadIdx.x & 31;
    if (gw >= P) return;
    int ia = a[gw];
    int ib = b[gw];
    float4 va = ((const float4*)(h + (size_t)ia * 128))[lane];
    float4 vb = ((const float4*)(h + (size_t)ib * 128))[lane];
    float s = va.x * vb.x + va.y * vb.y + va.z * vb.z + va.w * vb.w;
#pragma unroll
    for (int o = 16; o > 0; o >>= 1) s += __shfl_xor_sync(0xFFFFFFFFu, s, o);
    if (lane == 0) out[gw] = s;
}

// ---------------- host-side CSR build + gather sequence ----------------
static void build_csr_and_gather(const float* h, const int* src, const int* dst, int E,
                                 int* hist, int* rowptr, int* cursor, int* csr,
                                 int* blocksums, float* agg)
{
    zero_int_kernel<<<128, 256>>>(hist, N_NODES);
    hist_kernel<<<(E + 255) / 256, 256>>>(dst, hist, E);
    scan1_kernel<<<SCAN_NB, 256>>>(hist, blocksums);
    scan2_kernel<<<1, 32>>>(blocksums, SCAN_NB, rowptr);
    scan3_kernel<<<SCAN_NB, 256>>>(hist, blocksums, rowptr, cursor);
    fill_kernel<<<(E + 255) / 256, 256>>>(src, dst, cursor, csr, E);
    gather_mean_kernel<<<(N_NODES * 32 + 255) / 256, 256>>>(h, csr, rowptr, agg);
}

extern "C" void kernel_launch(void* const* d_in, const int* in_sizes, int n_in,
                              void* d_out, int out_size)
{
    const float* feat    = (const float*)d_in[0];
    const int*   e0s     = (const int*)d_in[1];
    const int*   e0d     = (const int*)d_in[2];
    const int*   e1s     = (const int*)d_in[3];
    const int*   e1d     = (const int*)d_in[4];
    const int*   ps      = (const int*)d_in[5];
    const int*   pd      = (const int*)d_in[6];
    const int*   ns      = (const int*)d_in[7];
    const int*   nd      = (const int*)d_in[8];
    const float* w_proj  = (const float*)d_in[9];
    const float* b_proj  = (const float*)d_in[10];
    const float* w_self1 = (const float*)d_in[11];
    const float* w_neigh1= (const float*)d_in[12];
    const float* b1      = (const float*)d_in[13];
    const float* w_self2 = (const float*)d_in[14];
    const float* w_neigh2= (const float*)d_in[15];
    const float* b2      = (const float*)d_in[16];

    const int E0 = in_sizes[1];
    const int E1 = in_sizes[3];
    const int P  = in_sizes[5];
    const int Q  = in_sizes[7];
    float* out = (float*)d_out;

    float *h0, *h1, *agg;
    int *hist, *rowptr, *cursor, *csr, *blocksums;
    cudaGetSymbolAddress((void**)&h0,  g_h0);
    cudaGetSymbolAddress((void**)&h1,  g_h1);
    cudaGetSymbolAddress((void**)&agg, g_agg);
    cudaGetSymbolAddress((void**)&hist, g_hist);
    cudaGetSymbolAddress((void**)&rowptr, g_rowptr);
    cudaGetSymbolAddress((void**)&cursor, g_cursor);
    cudaGetSymbolAddress((void**)&csr, g_csr);
    cudaGetSymbolAddress((void**)&blocksums, g_blocksums);

    const int gemm_grid = (N_NODES + 127) / 128;

    // h0 = relu(feat @ w_proj + b_proj)
    gemm_kernel<1><<<gemm_grid, 256>>>(feat, w_proj, b_proj, h0, N_NODES);

    // ---- layer 1 ----
    build_csr_and_gather(h0, e0s, e0d, E0, hist, rowptr, cursor, csr, blocksums, agg);
    dual_gemm_kernel<1><<<gemm_grid, 256>>>(h0, w_self1, agg, w_neigh1, b1, h1, N_NODES);

    // ---- layer 2 ----
    build_csr_and_gather(h1, e1s, e1d, E1, hist, rowptr, cursor, csr, blocksums, agg);
    dual_gemm_kernel<0><<<gemm_grid, 256>>>(h1, w_self2, agg, w_neigh2, b2, h0, N_NODES);

    // ---- scores ----
    score_kernel<<<(P + 7) / 8, 256>>>(h0, ps, pd, out, P);
    score_kernel<<<(Q + 7) / 8, 256>>>(h0, ns, nd, out + P, Q);
}